// round 2
// baseline (speedup 1.0000x reference)
#include <cuda_runtime.h>
#include <cuda_bf16.h>
#include <float.h>

// FiltrationLayer: per row of 4096 fp32, pivot = 2nd-largest value,
// out = 1.0f where x >= pivot else 0.0f (exact forward of the straight-through ref).

#define ROW_LEN 4096
#define THREADS 256
#define VEC_PER_THREAD 4   // 4 x float4 = 16 floats/thread, 256*16 = 4096

__device__ __forceinline__ void merge_val(float x, float& t1, float& t2) {
    // merge single value into running top-2 (duplicates counted)
    float hi = fmaxf(t1, x);
    float lo = fminf(t1, x);
    t2 = fmaxf(t2, lo);
    t1 = hi;
}

__device__ __forceinline__ void merge_pair(float b1, float b2, float& t1, float& t2) {
    // merge top-2 pair (b1>=b2) into running top-2
    float hi = fmaxf(t1, b1);
    float lo = fminf(t1, b1);
    t2 = fmaxf(fmaxf(t2, b2), lo);
    t1 = hi;
}

__global__ __launch_bounds__(THREADS, 8)
void filtration_top2_kernel(const float* __restrict__ in, float* __restrict__ out) {
    const long long row = blockIdx.x;
    const float4* __restrict__ inp = reinterpret_cast<const float4*>(in + row * ROW_LEN);
    float4* __restrict__ outp = reinterpret_cast<float4*>(out + row * ROW_LEN);

    const int t = threadIdx.x;

    // Load 16 floats per thread, coalesced float4 stride-256
    float4 v[VEC_PER_THREAD];
#pragma unroll
    for (int k = 0; k < VEC_PER_THREAD; k++)
        v[k] = inp[t + k * THREADS];

    // Local top-2
    float t1 = -FLT_MAX, t2 = -FLT_MAX;
#pragma unroll
    for (int k = 0; k < VEC_PER_THREAD; k++) {
        merge_val(v[k].x, t1, t2);
        merge_val(v[k].y, t1, t2);
        merge_val(v[k].z, t1, t2);
        merge_val(v[k].w, t1, t2);
    }

    // Warp reduce (top-2 pair merge via butterfly shuffle)
#pragma unroll
    for (int off = 16; off > 0; off >>= 1) {
        float o1 = __shfl_xor_sync(0xFFFFFFFFu, t1, off);
        float o2 = __shfl_xor_sync(0xFFFFFFFFu, t2, off);
        merge_pair(o1, o2, t1, t2);
    }

    // Cross-warp reduce: 8 warps -> smem -> every thread merges all 8 pairs
    __shared__ float s1[THREADS / 32], s2[THREADS / 32];
    const int warp = t >> 5;
    const int lane = t & 31;
    if (lane == 0) { s1[warp] = t1; s2[warp] = t2; }
    __syncthreads();

    float r1 = -FLT_MAX, r2 = -FLT_MAX;
#pragma unroll
    for (int w = 0; w < THREADS / 32; w++)
        merge_pair(s1[w], s2[w], r1, r2);

    const float pivot = r2;  // 2nd largest in the row

    // Binary output: 1.0 where kept (x >= pivot), 0.0 where masked
#pragma unroll
    for (int k = 0; k < VEC_PER_THREAD; k++) {
        float4 o;
        o.x = (v[k].x >= pivot) ? 1.0f : 0.0f;
        o.y = (v[k].y >= pivot) ? 1.0f : 0.0f;
        o.z = (v[k].z >= pivot) ? 1.0f : 0.0f;
        o.w = (v[k].w >= pivot) ? 1.0f : 0.0f;
        outp[t + k * THREADS] = o;
    }
}

extern "C" void kernel_launch(void* const* d_in, const int* in_sizes, int n_in,
                              void* d_out, int out_size) {
    const float* in = (const float*)d_in[0];
    float* out = (float*)d_out;
    const int n = in_sizes[0];
    const int rows = n / ROW_LEN;  // 16*2048 = 32768
    filtration_top2_kernel<<<rows, THREADS>>>(in, out);
}

// round 3
// speedup vs baseline: 1.0050x; 1.0050x over previous
#include <cuda_runtime.h>
#include <cuda_bf16.h>
#include <float.h>

// FiltrationLayer: per row of 4096 fp32, pivot = 2nd-largest value,
// out = 1.0f where x >= pivot else 0.0f (exact forward of the straight-through ref).

#define ROW_LEN 4096
#define THREADS 256
#define VEC_PER_THREAD 4   // 4 x float4 = 16 floats/thread, 256*16 = 4096

__device__ __forceinline__ void merge_val(float x, float& t1, float& t2) {
    // merge single value into running top-2 (duplicates counted)
    float hi = fmaxf(t1, x);
    float lo = fminf(t1, x);
    t2 = fmaxf(t2, lo);
    t1 = hi;
}

__device__ __forceinline__ void merge_pair(float b1, float b2, float& t1, float& t2) {
    // merge top-2 pair (b1>=b2) into running top-2
    float hi = fmaxf(t1, b1);
    float lo = fminf(t1, b1);
    t2 = fmaxf(fmaxf(t2, b2), lo);
    t1 = hi;
}

__global__ __launch_bounds__(THREADS, 8)
void filtration_top2_kernel(const float* __restrict__ in, float* __restrict__ out) {
    const long long row = blockIdx.x;
    const float4* __restrict__ inp = reinterpret_cast<const float4*>(in + row * ROW_LEN);
    float4* __restrict__ outp = reinterpret_cast<float4*>(out + row * ROW_LEN);

    const int t = threadIdx.x;

    // Load 16 floats per thread, coalesced float4 stride-256
    float4 v[VEC_PER_THREAD];
#pragma unroll
    for (int k = 0; k < VEC_PER_THREAD; k++)
        v[k] = inp[t + k * THREADS];

    // Local top-2
    float t1 = -FLT_MAX, t2 = -FLT_MAX;
#pragma unroll
    for (int k = 0; k < VEC_PER_THREAD; k++) {
        merge_val(v[k].x, t1, t2);
        merge_val(v[k].y, t1, t2);
        merge_val(v[k].z, t1, t2);
        merge_val(v[k].w, t1, t2);
    }

    // Warp reduce (top-2 pair merge via butterfly shuffle)
#pragma unroll
    for (int off = 16; off > 0; off >>= 1) {
        float o1 = __shfl_xor_sync(0xFFFFFFFFu, t1, off);
        float o2 = __shfl_xor_sync(0xFFFFFFFFu, t2, off);
        merge_pair(o1, o2, t1, t2);
    }

    // Cross-warp reduce: 8 warps -> smem -> every thread merges all 8 pairs
    __shared__ float s1[THREADS / 32], s2[THREADS / 32];
    const int warp = t >> 5;
    const int lane = t & 31;
    if (lane == 0) { s1[warp] = t1; s2[warp] = t2; }
    __syncthreads();

    float r1 = -FLT_MAX, r2 = -FLT_MAX;
#pragma unroll
    for (int w = 0; w < THREADS / 32; w++)
        merge_pair(s1[w], s2[w], r1, r2);

    const float pivot = r2;  // 2nd largest in the row

    // Binary output: 1.0 where kept (x >= pivot), 0.0 where masked
#pragma unroll
    for (int k = 0; k < VEC_PER_THREAD; k++) {
        float4 o;
        o.x = (v[k].x >= pivot) ? 1.0f : 0.0f;
        o.y = (v[k].y >= pivot) ? 1.0f : 0.0f;
        o.z = (v[k].z >= pivot) ? 1.0f : 0.0f;
        o.w = (v[k].w >= pivot) ? 1.0f : 0.0f;
        outp[t + k * THREADS] = o;
    }
}

extern "C" void kernel_launch(void* const* d_in, const int* in_sizes, int n_in,
                              void* d_out, int out_size) {
    const float* in = (const float*)d_in[0];
    float* out = (float*)d_out;
    const int n = in_sizes[0];
    const int rows = n / ROW_LEN;  // 16*2048 = 32768
    filtration_top2_kernel<<<rows, THREADS>>>(in, out);
}

// round 4
// speedup vs baseline: 1.0054x; 1.0004x over previous
#include <cuda_runtime.h>
#include <cuda_bf16.h>
#include <float.h>

// FiltrationLayer: per row of 4096 fp32, pivot = 2nd-largest value,
// out = 1.0f where x >= pivot else 0.0f (exact forward of the straight-through ref).
//
// R3: HBM-bound at 82% DRAM / 6715 GB/s. This round: streaming cache hints
// (__ldcs / __stcs) — input is read once and output written once, so evict-first
// on both keeps L2 from double-buffering two dead streams; target 86-88% DRAM.

#define ROW_LEN 4096
#define THREADS 256
#define VEC_PER_THREAD 4   // 4 x float4 = 16 floats/thread, 256*16 = 4096

__device__ __forceinline__ void merge_val(float x, float& t1, float& t2) {
    // merge single value into running top-2 (duplicates counted)
    float hi = fmaxf(t1, x);
    float lo = fminf(t1, x);
    t2 = fmaxf(t2, lo);
    t1 = hi;
}

__device__ __forceinline__ void merge_pair(float b1, float b2, float& t1, float& t2) {
    // merge top-2 pair (b1>=b2) into running top-2
    float hi = fmaxf(t1, b1);
    float lo = fminf(t1, b1);
    t2 = fmaxf(fmaxf(t2, b2), lo);
    t1 = hi;
}

__device__ __forceinline__ float sel01(float x, float pivot) {
    // 1.0f where x >= pivot else 0.0f, branch/select-free:
    // mask = all-ones when kept, AND with bit pattern of 1.0f
    unsigned m = (unsigned)-(int)(x >= pivot);
    return __uint_as_float(0x3f800000u & m);
}

__global__ __launch_bounds__(THREADS, 8)
void filtration_top2_kernel(const float* __restrict__ in, float* __restrict__ out) {
    const long long row = blockIdx.x;
    const float4* __restrict__ inp = reinterpret_cast<const float4*>(in + row * ROW_LEN);
    float4* __restrict__ outp = reinterpret_cast<float4*>(out + row * ROW_LEN);

    const int t = threadIdx.x;

    // Load 16 floats per thread, coalesced float4 stride-256, evict-first
    float4 v[VEC_PER_THREAD];
#pragma unroll
    for (int k = 0; k < VEC_PER_THREAD; k++)
        v[k] = __ldcs(&inp[t + k * THREADS]);

    // Local top-2
    float t1 = -FLT_MAX, t2 = -FLT_MAX;
#pragma unroll
    for (int k = 0; k < VEC_PER_THREAD; k++) {
        merge_val(v[k].x, t1, t2);
        merge_val(v[k].y, t1, t2);
        merge_val(v[k].z, t1, t2);
        merge_val(v[k].w, t1, t2);
    }

    // Warp reduce (top-2 pair merge via butterfly shuffle)
#pragma unroll
    for (int off = 16; off > 0; off >>= 1) {
        float o1 = __shfl_xor_sync(0xFFFFFFFFu, t1, off);
        float o2 = __shfl_xor_sync(0xFFFFFFFFu, t2, off);
        merge_pair(o1, o2, t1, t2);
    }

    // Cross-warp reduce: 8 warps -> smem -> every thread merges all 8 pairs
    __shared__ float s1[THREADS / 32], s2[THREADS / 32];
    const int warp = t >> 5;
    const int lane = t & 31;
    if (lane == 0) { s1[warp] = t1; s2[warp] = t2; }
    __syncthreads();

    float r1 = -FLT_MAX, r2 = -FLT_MAX;
#pragma unroll
    for (int w = 0; w < THREADS / 32; w++)
        merge_pair(s1[w], s2[w], r1, r2);

    const float pivot = r2;  // 2nd largest in the row

    // Binary output: 1.0 where kept (x >= pivot), 0.0 where masked. Streaming store.
#pragma unroll
    for (int k = 0; k < VEC_PER_THREAD; k++) {
        float4 o;
        o.x = sel01(v[k].x, pivot);
        o.y = sel01(v[k].y, pivot);
        o.z = sel01(v[k].z, pivot);
        o.w = sel01(v[k].w, pivot);
        __stcs(&outp[t + k * THREADS], o);
    }
}

extern "C" void kernel_launch(void* const* d_in, const int* in_sizes, int n_in,
                              void* d_out, int out_size) {
    const float* in = (const float*)d_in[0];
    float* out = (float*)d_out;
    const int n = in_sizes[0];
    const int rows = n / ROW_LEN;  // 16*2048 = 32768
    filtration_top2_kernel<<<rows, THREADS>>>(in, out);
}